// round 1
// baseline (speedup 1.0000x reference)
#include <cuda_runtime.h>
#include <math.h>

#define HH 512
#define WW 512
#define RR 4
#define NIMG 64
#define NEL (NIMG*HH*WW)
#define TC 128            // tile cols (threads per block)
#define TRR 128           // tile rows
#define BW (TC + 2*RR)    // row buffer width = 136

// Scratch (device globals: no allocation allowed in kernel_launch)
__device__ double g_partial[2048];
__device__ float  g_invSf;
__device__ float  g_A[NEL];
__device__ float  g_Bv[NEL];

// ---------------- Stage 1: deterministic global sum of |a| + 1e-12 (fp64) ----
__global__ void k_sum_partial(const float* __restrict__ a) {
    __shared__ double wsum[8];
    const int b = blockIdx.x, t = threadIdx.x;
    const float* p = a + (size_t)b * 8192;
    double acc = 0.0;
    #pragma unroll 8
    for (int j = t; j < 8192; j += 256) {
        acc += fabs((double)p[j]) + 1e-12;
    }
    #pragma unroll
    for (int o = 16; o > 0; o >>= 1) acc += __shfl_down_sync(0xffffffffu, acc, o);
    if ((t & 31) == 0) wsum[t >> 5] = acc;
    __syncthreads();
    if (t == 0) {
        double s = 0.0;
        #pragma unroll
        for (int w = 0; w < 8; w++) s += wsum[w];
        g_partial[b] = s;
    }
}

__global__ void k_sum_final() {
    __shared__ double wsum[8];
    const int t = threadIdx.x;
    double acc = 0.0;
    for (int j = t; j < 2048; j += 256) acc += g_partial[j];
    #pragma unroll
    for (int o = 16; o > 0; o >>= 1) acc += __shfl_down_sync(0xffffffffu, acc, o);
    if ((t & 31) == 0) wsum[t >> 5] = acc;
    __syncthreads();
    if (t == 0) {
        double s = 0.0;
        for (int w = 0; w < 8; w++) s += wsum[w];
        g_invSf = (float)(1.0 / s);
    }
}

// ---------------- Stage 2: fused 6-quantity box filter -> A, b -----------------
// One thread per output column; serial down rows. Horizontal 9-tap from shared
// row buffer (double-buffered, 1 sync/row); vertical sliding window via
// register accumulators + 9-deep per-thread ring in shared (no sync needed).
__global__ __launch_bounds__(TC) void k_stats(
    const float* __restrict__ X, const float* __restrict__ Y,
    const float* __restrict__ Wt)
{
    __shared__ float rb[2][3][BW];
    __shared__ float vring[9][6][TC];
    const int t   = threadIdx.x;
    const int img = blockIdx.z;
    const int bc  = blockIdx.x * TC;
    const int br  = blockIdx.y * TRR;
    const size_t ibase = (size_t)img * (HH * WW);
    const float* __restrict__ xim = X  + ibase;
    const float* __restrict__ yim = Y  + ibase;
    const float* __restrict__ aim = Wt + ibase;
    const float invS = g_invSf;

    const int col = bc + t;
    const int ncl = min(col + RR, WW - 1) - max(col - RR, 0) + 1;

    float acc0=0.f, acc1=0.f, acc2=0.f, acc3=0.f, acc4=0.f, acc5=0.f;
    int slot = 0;

    for (int k = 0; k < TRR + 2 * RR; ++k) {
        const int r = br - RR + k;
        const int p = k & 1;
        if (r >= 0 && r < HH) {
            const float* __restrict__ xr = xim + (size_t)r * WW;
            const float* __restrict__ yr = yim + (size_t)r * WW;
            const float* __restrict__ ar = aim + (size_t)r * WW;
            #pragma unroll
            for (int i = t; i < BW; i += TC) {
                const int gc = bc - RR + i;
                float xv = 0.f, yv = 0.f, av = 0.f;
                if (gc >= 0 && gc < WW) {
                    xv = xr[gc];
                    yv = yr[gc];
                    av = fabsf(ar[gc]) + 1e-12f;
                }
                rb[p][0][i] = xv; rb[p][1][i] = yv; rb[p][2][i] = av;
            }
        } else {
            #pragma unroll
            for (int i = t; i < BW; i += TC) {
                rb[p][0][i] = 0.f; rb[p][1][i] = 0.f; rb[p][2][i] = 0.f;
            }
        }
        __syncthreads();

        // horizontal 9-tap box of the 6 products
        float h0=0.f, h1=0.f, h2=0.f, h3=0.f, h4=0.f, h5=0.f;
        #pragma unroll
        for (int d = 0; d < 9; ++d) {
            const float xv  = rb[p][0][t + d];
            const float yv  = rb[p][1][t + d];
            const float av  = rb[p][2][t + d];
            const float ax  = av * xv;
            const float a2x = ax * av;
            h0 += av;                     // a
            h5 += ax;                     // a x
            h2 += a2x;                    // a^2 x
            h3 = fmaf(av,  yv, h3);       // a y
            h1 = fmaf(a2x, yv, h1);       // a^2 x y
            h4 = fmaf(a2x, xv, h4);       // a^2 x^2
        }

        // vertical sliding window (per-thread private ring slots -> no sync)
        if (k >= 9) {
            acc0 -= vring[slot][0][t];
            acc1 -= vring[slot][1][t];
            acc2 -= vring[slot][2][t];
            acc3 -= vring[slot][3][t];
            acc4 -= vring[slot][4][t];
            acc5 -= vring[slot][5][t];
        }
        acc0 += h0; acc1 += h1; acc2 += h2; acc3 += h3; acc4 += h4; acc5 += h5;
        vring[slot][0][t] = h0;
        vring[slot][1][t] = h1;
        vring[slot][2][t] = h2;
        vring[slot][3][t] = h3;
        vring[slot][4][t] = h4;
        vring[slot][5][t] = h5;
        if (++slot == 9) slot = 0;

        if (k >= 2 * RR) {
            const int ro = r - RR;
            const int nr = min(ro + RR, HH - 1) - max(ro - RR, 0) + 1;
            const float Nf  = (float)(nr * ncl);
            const float num = fmaf(-(acc2 * acc3), invS, acc1);
            const float den = fabsf(fmaf(-(acc2 * acc5), invS, acc4)) + Nf * 1e-8f;
            const float Av  = __fdividef(num, den);
            const float bv  = __fdividef(fmaf(-Av, acc5, acc3), acc0);
            const size_t o  = ibase + (size_t)ro * WW + col;
            g_A[o]  = Av;
            g_Bv[o] = bv;
        }
    }
}

// ---------------- Stage 3: box filter A,b + final blend ------------------------
__global__ __launch_bounds__(TC) void k_final(
    const float* __restrict__ X, float* __restrict__ out)
{
    __shared__ float rb[2][2][BW];
    __shared__ float vring[9][2][TC];
    const int t   = threadIdx.x;
    const int img = blockIdx.z;
    const int bc  = blockIdx.x * TC;
    const int br  = blockIdx.y * TRR;
    const size_t ibase = (size_t)img * (HH * WW);

    const int col = bc + t;
    const int ncl = min(col + RR, WW - 1) - max(col - RR, 0) + 1;

    float accA = 0.f, accB = 0.f;
    int slot = 0;

    for (int k = 0; k < TRR + 2 * RR; ++k) {
        const int r = br - RR + k;
        const int p = k & 1;
        if (r >= 0 && r < HH) {
            const float* __restrict__ Ar = g_A  + ibase + (size_t)r * WW;
            const float* __restrict__ Br = g_Bv + ibase + (size_t)r * WW;
            #pragma unroll
            for (int i = t; i < BW; i += TC) {
                const int gc = bc - RR + i;
                float av = 0.f, bv = 0.f;
                if (gc >= 0 && gc < WW) { av = Ar[gc]; bv = Br[gc]; }
                rb[p][0][i] = av; rb[p][1][i] = bv;
            }
        } else {
            #pragma unroll
            for (int i = t; i < BW; i += TC) {
                rb[p][0][i] = 0.f; rb[p][1][i] = 0.f;
            }
        }
        __syncthreads();

        float hA = 0.f, hB = 0.f;
        #pragma unroll
        for (int d = 0; d < 9; ++d) {
            hA += rb[p][0][t + d];
            hB += rb[p][1][t + d];
        }
        if (k >= 9) { accA -= vring[slot][0][t]; accB -= vring[slot][1][t]; }
        accA += hA; accB += hB;
        vring[slot][0][t] = hA; vring[slot][1][t] = hB;
        if (++slot == 9) slot = 0;

        if (k >= 2 * RR) {
            const int ro = r - RR;
            const int nr = min(ro + RR, HH - 1) - max(ro - RR, 0) + 1;
            const float rcpN = __fdividef(1.f, (float)(nr * ncl));
            const size_t o = ibase + (size_t)ro * WW + col;
            const float xv = X[o];
            out[o] = (accA * xv + accB) * rcpN;
        }
    }
}

extern "C" void kernel_launch(void* const* d_in, const int* in_sizes, int n_in,
                              void* d_out, int out_size) {
    const float* x = (const float*)d_in[0];  // lr_x
    const float* y = (const float*)d_in[1];  // lr_y
    const float* a = (const float*)d_in[2];  // l_a
    float* out = (float*)d_out;

    k_sum_partial<<<2048, 256>>>(a);
    k_sum_final<<<1, 256>>>();

    dim3 grid(WW / TC, HH / TRR, NIMG);
    k_stats<<<grid, TC>>>(x, y, a);
    k_final<<<grid, TC>>>(x, out);
}